// round 1
// baseline (speedup 1.0000x reference)
#include <cuda_runtime.h>
#include <cstdint>

// ---------------------------------------------------------------------------
// SelfAttentionWithPE: B=8, E=512, H=W=32 (S=1024), heads=8, head_dim=64, fp32
//
// Pipeline:
//   k_transpose_pe : x[b,E,32,32] -> xt[b*s, E]  (+positional encoding)
//   k_gemm (x3)    : xt @ {wq,wk,wv} + bias -> q/k/v in [b,h,s,d]
//   k_flash        : online-softmax attention -> att[b*s, E]
//   k_gemm (final) : att @ wo + bo -> out[b, E, 32, 32]
// ---------------------------------------------------------------------------

#define BATCH 8
#define EMB   512
#define SEQ   1024
#define NH    8
#define HD    64
#define MTOT  (BATCH * SEQ)         // 8192
#define SCALE 0.125f                // 1/sqrt(64)
#define FULLMASK 0xffffffffu

// Scratch: xt, q, k, v, att  (5 x 16.78 MB = 83.9 MB)
__device__ float g_scratch[5u * MTOT * EMB];

// ---------------------------------------------------------------------------
// Kernel 1: transpose [b,E,s] -> [b,s,E] tile-wise + positional encoding
// grid (E/32, S/32, B), block (32, 8)
// ---------------------------------------------------------------------------
__global__ void k_transpose_pe(const float* __restrict__ x,
                               const float* __restrict__ pos_w,
                               const float* __restrict__ pos_b,
                               float* __restrict__ xt)
{
    __shared__ float tile[32][33];
    const int e0 = blockIdx.x * 32;
    const int s0 = blockIdx.y * 32;
    const int b  = blockIdx.z;
    const int tx = threadIdx.x;       // 0..31
    const int ty = threadIdx.y;       // 0..7

    // load: x[b, e0+el, s0+tx], coalesced along s
#pragma unroll
    for (int i = 0; i < 4; i++) {
        int el = ty + i * 8;
        tile[el][tx] = x[((size_t)(b * EMB + e0 + el)) * SEQ + s0 + tx];
    }
    __syncthreads();

    // store: xt[(b*SEQ + s0+sl)*EMB + e0+tx], coalesced along e, add PE
    const int e = e0 + tx;
    const float pw0 = pos_w[e];
    const float pw1 = pos_w[EMB + e];
    const float pb  = pos_b[e];
#pragma unroll
    for (int i = 0; i < 4; i++) {
        int sl = ty + i * 8;
        int s  = s0 + sl;
        float row = (float)(s >> 5);
        float col = (float)(s & 31);
        float v = tile[tx][sl] + row * pw0 + col * pw1 + pb;
        xt[((size_t)(b * SEQ + s)) * EMB + e] = v;
    }
}

// ---------------------------------------------------------------------------
// Kernel 2: GEMM  C[M=8192, N=512] = A[M,512] @ W[512,512] + bias
// BM=BN=64, BK=16, 256 threads, 4x4 microtile (strided layout).
// mode 0: scatter to q/k/v layout [b,h,s,d]  (e = h*64+d)
// mode 1: scatter to final output [b, c=n, 32, 32]  (pixel = m % 1024)
// grid (N/64=8, M/64=128), block 256
// ---------------------------------------------------------------------------
__global__ void k_gemm(const float* __restrict__ A,
                       const float* __restrict__ W,
                       const float* __restrict__ bias,
                       float* __restrict__ out,
                       int mode)
{
    __shared__ float As[16][65];   // [k][m], padded
    __shared__ float Bs[16][64];   // [k][n]

    const int tid = threadIdx.x;
    const int tx  = tid & 15;
    const int ty  = tid >> 4;
    const int m0  = blockIdx.y * 64;
    const int n0  = blockIdx.x * 64;
    const int K = EMB, N = EMB;

    float acc[4][4];
#pragma unroll
    for (int i = 0; i < 4; i++)
#pragma unroll
        for (int j = 0; j < 4; j++) acc[i][j] = 0.0f;

    for (int k0 = 0; k0 < K; k0 += 16) {
        // A tile 64x16 -> As[k][m]
#pragma unroll
        for (int p = 0; p < 4; p++) {
            int ml = (tid >> 4) + p * 16;
            int kl = tid & 15;
            As[kl][ml] = A[(size_t)(m0 + ml) * K + k0 + kl];
        }
        // W tile 16x64 -> Bs[k][n]
#pragma unroll
        for (int p = 0; p < 4; p++) {
            int kl = (tid >> 6) + p * 4;
            int nl = tid & 63;
            Bs[kl][nl] = W[(size_t)(k0 + kl) * N + n0 + nl];
        }
        __syncthreads();

#pragma unroll
        for (int kk = 0; kk < 16; kk++) {
            float a[4], bb[4];
#pragma unroll
            for (int i = 0; i < 4; i++) a[i]  = As[kk][ty + 16 * i];
#pragma unroll
            for (int j = 0; j < 4; j++) bb[j] = Bs[kk][tx + 16 * j];
#pragma unroll
            for (int i = 0; i < 4; i++)
#pragma unroll
                for (int j = 0; j < 4; j++) acc[i][j] += a[i] * bb[j];
        }
        __syncthreads();
    }

#pragma unroll
    for (int i = 0; i < 4; i++) {
        int m = m0 + ty + 16 * i;
        int b = m >> 10;
        int s = m & 1023;
#pragma unroll
        for (int j = 0; j < 4; j++) {
            int n = n0 + tx + 16 * j;
            float v = acc[i][j] + bias[n];
            if (mode == 0) {
                int h = n >> 6, d = n & 63;
                out[((size_t)((b * NH + h) * SEQ + s)) * HD + d] = v;
            } else {
                // final: out[b, c=n, pixel=s]
                out[((size_t)(b * EMB + n)) * SEQ + s] = v;
            }
        }
    }
}

// ---------------------------------------------------------------------------
// Kernel 3: flash attention.
// grid (S/64 = 16, B*NH = 64), block 256 (8 warps x 8 q-rows each).
// Q tile [64,64] in smem. K tiles of 32 keys. Online softmax in registers.
// PV via warp shuffles (p owned by lane == key column).
// Output written to att[b*s, E] layout (e = h*64 + d).
// ---------------------------------------------------------------------------
__global__ void k_flash(const float* __restrict__ Q,
                        const float* __restrict__ K,
                        const float* __restrict__ V,
                        float* __restrict__ O)
{
    __shared__ __align__(16) float Qs[64][64];
    __shared__ __align__(16) float Ks[32][68];   // padded, 16B-aligned rows
    __shared__ __align__(16) float Vs[32][64];

    const int bh = blockIdx.y;                  // b*8 + h
    const int q0 = blockIdx.x * 64;
    const size_t base = (size_t)bh * SEQ * HD;
    const float* Qb = Q + base;
    const float* Kb = K + base;
    const float* Vb = V + base;

    const int tid  = threadIdx.x;
    const int warp = tid >> 5;
    const int lane = tid & 31;
    const int r0   = warp * 8;                  // this warp's first q row (local)

    // load Q tile (64x64)
    for (int i = tid; i < 64 * 64; i += 256) {
        Qs[i >> 6][i & 63] = Qb[(size_t)(q0 + (i >> 6)) * HD + (i & 63)];
    }

    float m_run[8], l_run[8], o0[8], o1[8];
#pragma unroll
    for (int r = 0; r < 8; r++) {
        m_run[r] = -1e30f; l_run[r] = 0.0f; o0[r] = 0.0f; o1[r] = 0.0f;
    }

    for (int kt = 0; kt < SEQ; kt += 32) {
        __syncthreads();    // protect smem tiles (also covers initial Q load)
        // load K,V tiles (32x64 each)
        for (int i = tid; i < 32 * 64; i += 256) {
            int rr = i >> 6, cc = i & 63;
            Ks[rr][cc] = Kb[(size_t)(kt + rr) * HD + cc];
            Vs[rr][cc] = Vb[(size_t)(kt + rr) * HD + cc];
        }
        __syncthreads();

        // scores: lane owns key column c = kt + lane
        float sacc[8];
#pragma unroll
        for (int r = 0; r < 8; r++) sacc[r] = 0.0f;
#pragma unroll
        for (int d4 = 0; d4 < 16; d4++) {
            float4 kv = *reinterpret_cast<const float4*>(&Ks[lane][d4 * 4]);
#pragma unroll
            for (int r = 0; r < 8; r++) {
                float4 qv = *reinterpret_cast<const float4*>(&Qs[r0 + r][d4 * 4]);
                sacc[r] += qv.x * kv.x + qv.y * kv.y + qv.z * kv.z + qv.w * kv.w;
            }
        }

        float p[8];
#pragma unroll
        for (int r = 0; r < 8; r++) {
            float s = sacc[r] * SCALE;
            // warp max over 32 key columns
            float mt = s;
#pragma unroll
            for (int off = 16; off > 0; off >>= 1)
                mt = fmaxf(mt, __shfl_xor_sync(FULLMASK, mt, off));
            float m_new = fmaxf(m_run[r], mt);
            float alpha = __expf(m_run[r] - m_new);
            float pv    = __expf(s - m_new);
            float ls = pv;
#pragma unroll
            for (int off = 16; off > 0; off >>= 1)
                ls += __shfl_xor_sync(FULLMASK, ls, off);
            l_run[r] = l_run[r] * alpha + ls;
            m_run[r] = m_new;
            o0[r] *= alpha;
            o1[r] *= alpha;
            p[r] = pv;
        }

        // PV: o[r][d] += sum_c p[r][c] * V[c][d];  d = lane, lane+32
#pragma unroll
        for (int c = 0; c < 32; c++) {
            float v0 = Vs[c][lane];
            float v1 = Vs[c][lane + 32];
#pragma unroll
            for (int r = 0; r < 8; r++) {
                float pc = __shfl_sync(FULLMASK, p[r], c);
                o0[r] += pc * v0;
                o1[r] += pc * v1;
            }
        }
    }

    // epilogue: att[(b*SEQ + s)*EMB + h*64 + d]
    const int b = bh >> 3, h = bh & 7;
#pragma unroll
    for (int r = 0; r < 8; r++) {
        float inv = 1.0f / l_run[r];
        int s = q0 + r0 + r;
        float* orow = O + ((size_t)(b * SEQ + s)) * EMB + h * HD;
        orow[lane]      = o0[r] * inv;
        orow[lane + 32] = o1[r] * inv;
    }
}

// ---------------------------------------------------------------------------
extern "C" void kernel_launch(void* const* d_in, const int* in_sizes, int n_in,
                              void* d_out, int out_size)
{
    const float* x     = (const float*)d_in[0];
    const float* pos_w = (const float*)d_in[1];
    const float* pos_b = (const float*)d_in[2];
    const float* wq    = (const float*)d_in[3];
    const float* bq    = (const float*)d_in[4];
    const float* wk    = (const float*)d_in[5];
    const float* bk    = (const float*)d_in[6];
    const float* wv    = (const float*)d_in[7];
    const float* bv    = (const float*)d_in[8];
    const float* wo    = (const float*)d_in[9];
    const float* bo    = (const float*)d_in[10];
    float* out = (float*)d_out;

    void* scratch_ptr = nullptr;
    cudaGetSymbolAddress(&scratch_ptr, g_scratch);
    float* g_xt  = (float*)scratch_ptr;
    float* g_q   = g_xt  + (size_t)MTOT * EMB;
    float* g_k   = g_q   + (size_t)MTOT * EMB;
    float* g_v   = g_k   + (size_t)MTOT * EMB;
    float* g_att = g_v   + (size_t)MTOT * EMB;

    // 1) transpose + positional encoding
    {
        dim3 grid(EMB / 32, SEQ / 32, BATCH);
        dim3 block(32, 8);
        k_transpose_pe<<<grid, block>>>(x, pos_w, pos_b, g_xt);
    }

    // 2) QKV projections
    {
        dim3 grid(EMB / 64, MTOT / 64);
        k_gemm<<<grid, 256>>>(g_xt, wq, bq, g_q, 0);
        k_gemm<<<grid, 256>>>(g_xt, wk, bk, g_k, 0);
        k_gemm<<<grid, 256>>>(g_xt, wv, bv, g_v, 0);
    }

    // 3) flash attention
    {
        dim3 grid(SEQ / 64, BATCH * NH);
        k_flash<<<grid, 256>>>(g_q, g_k, g_v, g_att);
    }

    // 4) output projection (+ scatter to [b,c,h,w])
    {
        dim3 grid(EMB / 64, MTOT / 64);
        k_gemm<<<grid, 256>>>(g_att, wo, bo, out, 1);
    }
}